// round 6
// baseline (speedup 1.0000x reference)
#include <cuda_runtime.h>
#include <cuda_bf16.h>
#include <cstdint>

#define NPTS 32768
#define DD   512
#define KC   4096
#define LC   3
#define NQ   ((size_t)NPTS * DD)
#define NIDX ((size_t)NPTS * LC)

#define MT 256
#define NTT 128
#define KT 32
#define STAGES 4
#define NKCH (DD / KT)          // 16
#define NTILES (KC / NTT)       // 32
#define MARGIN 2.0f

// stage: A 16KB + B 8KB = 24KB; 4 stages = 96KB; cnorm 512B
#define SMEM_STAGE 24576
#define STAGE_B_OFF 16384
#define OFF_CS 98304
#define SMEM_TOTAL 98816

__device__ float          g_resid[NPTS * DD];
__device__ __nv_bfloat16  g_ahi[NPTS * DD];
__device__ __nv_bfloat16  g_bhi[LC * KC * DD];
__device__ float          g_c[LC * KC];
__device__ float4         g_ts[NPTS * NTILES];   // per-tile top-4 scores
__device__ int4           g_ti[NPTS * NTILES];   // per-tile top-4 indices
__device__ float          g_s5[NPTS * NTILES];   // per-tile 5th-best score
__device__ int            g_counts[LC * KC];
__device__ double         g_commit;
__device__ float          g_perp[LC];

__device__ __forceinline__ uint32_t smem_u32(const void* p) {
    uint32_t a;
    asm("{ .reg .u64 t; cvta.to.shared.u64 t, %1; cvt.u32.u64 %0, t; }" : "=r"(a) : "l"(p));
    return a;
}
#define CP_ASYNC16(dst, src) asm volatile("cp.async.cg.shared.global [%0], [%1], 16;" :: "r"(dst), "l"(src))
#define CP_COMMIT() asm volatile("cp.async.commit_group;" ::: "memory")
#define CP_WAIT2()  asm volatile("cp.async.wait_group 2;" ::: "memory")

__device__ __forceinline__ void ldmat4(uint32_t* r, uint32_t addr) {
    asm volatile("ldmatrix.sync.aligned.m8n8.x4.shared.b16 {%0,%1,%2,%3}, [%4];"
        : "=r"(r[0]), "=r"(r[1]), "=r"(r[2]), "=r"(r[3]) : "r"(addr));
}
__device__ __forceinline__ void mma_bf16(float* d, const uint32_t* a, const uint32_t* b) {
    asm volatile("mma.sync.aligned.m16n8k16.row.col.f32.bf16.bf16.f32 "
        "{%0,%1,%2,%3}, {%4,%5,%6,%7}, {%8,%9}, {%0,%1,%2,%3};"
        : "+f"(d[0]), "+f"(d[1]), "+f"(d[2]), "+f"(d[3])
        : "r"(a[0]), "r"(a[1]), "r"(a[2]), "r"(a[3]), "r"(b[0]), "r"(b[1]));
}
__device__ __forceinline__ uint32_t swz(int r, int v) {
    return (uint32_t)((r * 4 + (v ^ ((r >> 1) & 3))) * 16);
}

__global__ void init_kernel() {
    int i = blockIdx.x * blockDim.x + threadIdx.x;
    if (i < LC * KC) g_counts[i] = 0;
    if (i == 0) g_commit = 0.0;
}
__global__ void cvt_z_kernel(const float* __restrict__ z) {
    size_t i = ((size_t)blockIdx.x * blockDim.x + threadIdx.x) * 4;
    if (i >= NQ) return;
    float4 v = *(const float4*)(z + i);
    ((__nv_bfloat162*)(g_ahi + i))[0] = __floats2bfloat162_rn(v.x, v.y);
    ((__nv_bfloat162*)(g_ahi + i))[1] = __floats2bfloat162_rn(v.z, v.w);
}
__global__ void cvt_cb_kernel(const float* __restrict__ cb) {
    size_t i = ((size_t)blockIdx.x * blockDim.x + threadIdx.x) * 4;
    if (i >= (size_t)LC * KC * DD) return;
    float4 v = *(const float4*)(cb + i);
    ((__nv_bfloat162*)(g_bhi + i))[0] = __floats2bfloat162_rn(v.x, v.y);
    ((__nv_bfloat162*)(g_bhi + i))[1] = __floats2bfloat162_rn(v.z, v.w);
}
__global__ void colnorm_kernel(const float* __restrict__ cb) {
    int warp = (blockIdx.x * blockDim.x + threadIdx.x) >> 5;
    int lane = threadIdx.x & 31;
    if (warp >= LC * KC) return;
    const float4* row = (const float4*)(cb + (size_t)warp * DD);
    float s = 0.f;
    #pragma unroll
    for (int i = lane; i < DD / 4; i += 32) {
        float4 v = row[i];
        s += v.x * v.x + v.y * v.y + v.z * v.z + v.w * v.w;
    }
    #pragma unroll
    for (int o = 16; o; o >>= 1) s += __shfl_down_sync(0xffffffffu, s, o);
    if (lane == 0) g_c[warp] = 0.5f * s;
}

// ---- coarse bf16 mma.sync GEMM 256x128 + per-tile top-4(+s5) epilogue ----
__global__ __launch_bounds__(256, 1) void gemm_kernel(int layer) {
    extern __shared__ char smem[];
    uint32_t sb = smem_u32(smem);
    int tid = threadIdx.x, wid = tid >> 5, lane = tid & 31;
    int warp_m = wid >> 1, warp_n = wid & 1;      // 4x2 warp grid, 64x64 warp tile
    int m0 = blockIdx.x * MT, n0 = blockIdx.y * NTT;
    const __nv_bfloat16* __restrict__ A = g_ahi;
    const __nv_bfloat16* __restrict__ B = g_bhi + (size_t)layer * KC * DD;
    const float* __restrict__ cl = g_c + layer * KC;
    float* cs = (float*)(smem + OFF_CS);
    if (tid < NTT) cs[tid] = cl[n0 + tid];

    // 1024 A-units + 512 B-units per stage; 256 threads x 6 cp.async
    auto load_stage = [&](int s, int kc) {
        uint32_t aBase = sb + s * SMEM_STAGE;
        uint32_t bBase = aBase + STAGE_B_OFF;
        #pragma unroll
        for (int i = 0; i < 6; i++) {
            int f = tid + i * 256;              // 0..1535
            if (f < 1024) {
                int r = f >> 2, v = f & 3;
                const __nv_bfloat16* src = A + (size_t)(m0 + r) * DD + kc * KT + v * 8;
                CP_ASYNC16(aBase + swz(r, v), src);
            } else {
                int g = f - 1024;
                int r = g >> 2, v = g & 3;
                const __nv_bfloat16* src = B + (size_t)(n0 + r) * DD + kc * KT + v * 8;
                CP_ASYNC16(bBase + swz(r, v), src);
            }
        }
    };

    float acc[4][8][4];
    #pragma unroll
    for (int mi = 0; mi < 4; mi++)
        #pragma unroll
        for (int ni = 0; ni < 8; ni++)
            #pragma unroll
            for (int e = 0; e < 4; e++) acc[mi][ni][e] = 0.f;

    #pragma unroll
    for (int s = 0; s < STAGES - 1; s++) { load_stage(s, s); CP_COMMIT(); }

    for (int kc = 0; kc < NKCH; kc++) {
        CP_WAIT2();
        __syncthreads();
        int st = kc & (STAGES - 1);
        uint32_t aBase = sb + st * SMEM_STAGE;
        uint32_t bBase = aBase + STAGE_B_OFF;
        #pragma unroll
        for (int kk = 0; kk < 2; kk++) {
            uint32_t af[4][4], bf[4][4];
            #pragma unroll
            for (int mi = 0; mi < 4; mi++) {
                int r = warp_m * 64 + mi * 16 + (lane & 15);
                int v = 2 * kk + (lane >> 4);
                ldmat4(af[mi], aBase + swz(r, v));
            }
            #pragma unroll
            for (int nh = 0; nh < 4; nh++) {
                int r = warp_n * 64 + nh * 16 + (lane & 7) + ((lane >> 4) << 3);
                int v = 2 * kk + ((lane >> 3) & 1);
                ldmat4(bf[nh], bBase + swz(r, v));
            }
            #pragma unroll
            for (int mi = 0; mi < 4; mi++)
                #pragma unroll
                for (int nh = 0; nh < 4; nh++) {
                    mma_bf16(acc[mi][2 * nh],     af[mi], &bf[nh][0]);
                    mma_bf16(acc[mi][2 * nh + 1], af[mi], &bf[nh][2]);
                }
        }
        __syncthreads();
        if (kc + STAGES - 1 < NKCH) load_stage((kc + STAGES - 1) & (STAGES - 1), kc + STAGES - 1);
        CP_COMMIT();
    }
    __syncthreads();

    // epilogue in two 128-row halves through 64KB smem score buffer
    float* scores = (float*)smem;
    #pragma unroll
    for (int h = 0; h < 2; h++) {
        if ((warp_m >> 1) == h) {
            int r0 = (warp_m & 1) * 64 + (lane >> 2);
            int c0 = warp_n * 64 + (lane & 3) * 2;
            #pragma unroll
            for (int mi = 0; mi < 4; mi++)
                #pragma unroll
                for (int ni = 0; ni < 8; ni++) {
                    int r = r0 + mi * 16, c = c0 + ni * 8;
                    scores[r * NTT + c]           = acc[mi][ni][0];
                    scores[r * NTT + c + 1]       = acc[mi][ni][1];
                    scores[(r + 8) * NTT + c]     = acc[mi][ni][2];
                    scores[(r + 8) * NTT + c + 1] = acc[mi][ni][3];
                }
        }
        __syncthreads();
        if (tid < 128) {
            int r = tid;
            float t1 = -3.0e38f, t2 = -3.0e38f, t3 = -3.0e38f, t4 = -3.0e38f, t5 = -3.0e38f;
            int j1 = 0, j2 = 0, j3 = 0, j4 = 0;
            #pragma unroll 8
            for (int j = 0; j < 32; j++) {
                int q = (j + r) & 31;
                float4 v = *(float4*)&scores[r * NTT + q * 4];
                #pragma unroll
                for (int e = 0; e < 4; e++) {
                    float sc = (&v.x)[e] - cs[q * 4 + e];
                    int col = n0 + q * 4 + e;
                    if (sc > t1)      { t5 = t4; t4 = t3; j4 = j3; t3 = t2; j3 = j2; t2 = t1; j2 = j1; t1 = sc; j1 = col; }
                    else if (sc > t2) { t5 = t4; t4 = t3; j4 = j3; t3 = t2; j3 = j2; t2 = sc; j2 = col; }
                    else if (sc > t3) { t5 = t4; t4 = t3; j4 = j3; t3 = sc; j3 = col; }
                    else if (sc > t4) { t5 = t4; t4 = sc; j4 = col; }
                    else if (sc > t5) { t5 = sc; }
                }
            }
            int row = m0 + h * 128 + r, t = blockIdx.y;
            g_ts[row * NTILES + t] = make_float4(t1, t2, t3, t4);
            g_ti[row * NTILES + t] = make_int4(j1, j2, j3, j4);
            g_s5[row * NTILES + t] = t5;
        }
        __syncthreads();
    }
}

// ---- fused exact re-rank + assign (warp per row) ----
template <bool LAST>
__global__ __launch_bounds__(128) void rerank_assign_kernel(
    const float* __restrict__ z, const float* __restrict__ cb,
    float* __restrict__ out_q, float* __restrict__ out_idx, int layer)
{
    int warp = (blockIdx.x * blockDim.x + threadIdx.x) >> 5;
    int lane = threadIdx.x & 31;
    if (warp >= NPTS) return;
    int row = warp;
    const float* Ar = (layer == 0) ? z + (size_t)row * DD : g_resid + (size_t)row * DD;
    const float* El = cb + (size_t)layer * KC * DD;
    const float* cl = g_c + layer * KC;

    float4 ts = g_ts[row * NTILES + lane];
    int4   ti = g_ti[row * NTILES + lane];
    float  s5 = g_s5[row * NTILES + lane];

    float best = ts.x;
    #pragma unroll
    for (int o = 16; o; o >>= 1) best = fmaxf(best, __shfl_xor_sync(0xffffffffu, best, o));
    float thr = best - MARGIN;
    bool slow = __any_sync(0xffffffffu, s5 >= thr);

    float a[16];
    #pragma unroll
    for (int j = 0; j < 4; j++) {
        float4 v = ((const float4*)Ar)[j * 32 + lane];
        a[j * 4 + 0] = v.x; a[j * 4 + 1] = v.y; a[j * 4 + 2] = v.z; a[j * 4 + 3] = v.w;
    }

    float bs = -3.0e38f; int bi = 0x7fffffff;
    auto eval = [&](int k) {
        const float4* E4 = (const float4*)(El + (size_t)k * DD);
        float s = 0.f;
        #pragma unroll
        for (int j = 0; j < 4; j++) {
            float4 e = E4[j * 32 + lane];
            s = fmaf(a[j * 4 + 0], e.x, s); s = fmaf(a[j * 4 + 1], e.y, s);
            s = fmaf(a[j * 4 + 2], e.z, s); s = fmaf(a[j * 4 + 3], e.w, s);
        }
        #pragma unroll
        for (int o = 16; o; o >>= 1) s += __shfl_xor_sync(0xffffffffu, s, o);
        s -= cl[k];
        if (s > bs || (s == bs && k < bi)) { bs = s; bi = k; }
    };

    if (slow) {
        for (int k = 0; k < KC; k++) eval(k);
    } else {
        unsigned m0b = __ballot_sync(0xffffffffu, ts.x >= thr);
        unsigned m1b = __ballot_sync(0xffffffffu, ts.y >= thr);
        unsigned m2b = __ballot_sync(0xffffffffu, ts.z >= thr);
        unsigned m3b = __ballot_sync(0xffffffffu, ts.w >= thr);
        int cnt = __popc(m0b) + __popc(m1b) + __popc(m2b) + __popc(m3b);
        if (cnt == 1) {
            int t = __ffs(m0b) - 1;
            bi = __shfl_sync(0xffffffffu, ti.x, t);
        } else {
            unsigned m = m0b;
            while (m) { int t = __ffs(m) - 1; m &= m - 1; eval(__shfl_sync(0xffffffffu, ti.x, t)); }
            m = m1b;
            while (m) { int t = __ffs(m) - 1; m &= m - 1; eval(__shfl_sync(0xffffffffu, ti.y, t)); }
            m = m2b;
            while (m) { int t = __ffs(m) - 1; m &= m - 1; eval(__shfl_sync(0xffffffffu, ti.z, t)); }
            m = m3b;
            while (m) { int t = __ffs(m) - 1; m &= m - 1; eval(__shfl_sync(0xffffffffu, ti.w, t)); }
        }
    }

    if (lane == 0) {
        out_idx[(size_t)row * LC + layer] = (float)bi;
        atomicAdd(&g_counts[layer * KC + bi], 1);
    }
    const float4* E4 = (const float4*)(El + (size_t)bi * DD);
    float csum = 0.f;
    #pragma unroll
    for (int j = 0; j < 4; j++) {
        float4 e = E4[j * 32 + lane];
        float4 rn = make_float4(a[j * 4 + 0] - e.x, a[j * 4 + 1] - e.y,
                                a[j * 4 + 2] - e.z, a[j * 4 + 3] - e.w);
        csum += rn.x * rn.x + rn.y * rn.y + rn.z * rn.z + rn.w * rn.w;
        if (LAST) {
            float4 zv = ((const float4*)(z + (size_t)row * DD))[j * 32 + lane];
            ((float4*)(out_q + (size_t)row * DD))[j * 32 + lane] =
                make_float4(zv.x - rn.x, zv.y - rn.y, zv.z - rn.z, zv.w - rn.w);
        } else {
            ((float4*)(g_resid + (size_t)row * DD))[j * 32 + lane] = rn;
            __nv_bfloat162* bh = (__nv_bfloat162*)(g_ahi + (size_t)row * DD + (j * 32 + lane) * 4);
            bh[0] = __floats2bfloat162_rn(rn.x, rn.y);
            bh[1] = __floats2bfloat162_rn(rn.z, rn.w);
        }
    }
    #pragma unroll
    for (int o = 16; o; o >>= 1) csum += __shfl_down_sync(0xffffffffu, csum, o);
    if (lane == 0) atomicAdd(&g_commit, (double)csum);
}

__global__ void perp_kernel() {
    int l = blockIdx.x, t = threadIdx.x;
    float local = 0.f;
    for (int k = t; k < KC; k += 256) {
        float p = (float)g_counts[l * KC + k] * (1.0f / (float)NPTS);
        local += p * logf(p + 1e-10f);
    }
    #pragma unroll
    for (int o = 16; o; o >>= 1) local += __shfl_down_sync(0xffffffffu, local, o);
    __shared__ float red[8];
    if ((t & 31) == 0) red[t >> 5] = local;
    __syncthreads();
    if (t == 0) {
        float s = 0.f;
        #pragma unroll
        for (int i = 0; i < 8; i++) s += red[i];
        g_perp[l] = expf(-s);
    }
}
__global__ void final_kernel(float* __restrict__ out_sc) {
    out_sc[0] = (float)(g_commit * (0.25 / (double)NQ));
    out_sc[1] = (g_perp[0] + g_perp[1] + g_perp[2]) * (1.0f / 3.0f);
}

extern "C" void kernel_launch(void* const* d_in, const int* in_sizes, int n_in,
                              void* d_out, int out_size)
{
    const float* z  = (const float*)d_in[0];
    const float* cb = (const float*)d_in[1];
    float* out = (float*)d_out;
    float* out_q   = out;
    float* out_idx = out + NQ;
    float* out_sc  = out_idx + NIDX;

    cudaFuncSetAttribute(gemm_kernel, cudaFuncAttributeMaxDynamicSharedMemorySize, SMEM_TOTAL);

    init_kernel<<<48, 256>>>();
    cvt_z_kernel<<<(int)(NQ / 4 / 256), 256>>>(z);
    cvt_cb_kernel<<<(int)((size_t)LC * KC * DD / 4 / 256), 256>>>(cb);
    colnorm_kernel<<<(LC * KC * 32 + 255) / 256, 256>>>(cb);

    dim3 gg(NPTS / MT, KC / NTT);
    for (int l = 0; l < LC; l++) {
        gemm_kernel<<<gg, 256, SMEM_TOTAL>>>(l);
        if (l < LC - 1)
            rerank_assign_kernel<false><<<NPTS / 4, 128>>>(z, cb, out_q, out_idx, l);
        else
            rerank_assign_kernel<true><<<NPTS / 4, 128>>>(z, cb, out_q, out_idx, l);
    }
    perp_kernel<<<LC, 256>>>();
    final_kernel<<<1, 1>>>(out_sc);
}

// round 7
// speedup vs baseline: 1.8730x; 1.8730x over previous
#include <cuda_runtime.h>
#include <cuda_bf16.h>
#include <cstdint>

#define NPTS 32768
#define DD   512
#define KC   4096
#define LC   3
#define NQ   ((size_t)NPTS * DD)
#define NIDX ((size_t)NPTS * LC)

#define MT 128
#define NTT 128
#define KT 64                    // int8 k per chunk (64 bytes/row)
#define STAGES 4
#define NKCH (DD / KT)           // 8
#define NTILES (KC / NTT)        // 32
#define MARGIN 8.0f

// stage: A 8KB + B 8KB = 16KB; 4 stages 64KB (reused as 128x128 f32 scores); + cs/sb/sa
#define SMEM_STAGE 16384
#define OFF_CS 65536
#define OFF_SB 66048
#define OFF_SA 66560
#define SMEM_TOTAL 67072

__device__ float   g_resid[NPTS * DD];     // fp32 residual (exact path)
__device__ int8_t  g_ai8[NPTS * DD];       // int8 residual/z
__device__ float   g_sa[NPTS];             // per-row A scale
__device__ int8_t  g_bi8[LC * KC * DD];    // int8 codebooks
__device__ float   g_sb[LC * KC];          // per-code B scale
__device__ float   g_c[LC * KC];           // 0.5*||E||^2 fp32 exact
__device__ float4  g_ts[NPTS * NTILES];
__device__ int4    g_ti[NPTS * NTILES];
__device__ float   g_s5[NPTS * NTILES];
__device__ int     g_counts[LC * KC];
__device__ double  g_commit;
__device__ float   g_perp[LC];

__device__ __forceinline__ uint32_t smem_u32(const void* p) {
    uint32_t a;
    asm("{ .reg .u64 t; cvta.to.shared.u64 t, %1; cvt.u32.u64 %0, t; }" : "=r"(a) : "l"(p));
    return a;
}
#define CP_ASYNC16(dst, src) asm volatile("cp.async.cg.shared.global [%0], [%1], 16;" :: "r"(dst), "l"(src))
#define CP_COMMIT() asm volatile("cp.async.commit_group;" ::: "memory")
#define CP_WAIT2()  asm volatile("cp.async.wait_group 2;" ::: "memory")

__device__ __forceinline__ void ldmat4(uint32_t* r, uint32_t addr) {
    asm volatile("ldmatrix.sync.aligned.m8n8.x4.shared.b16 {%0,%1,%2,%3}, [%4];"
        : "=r"(r[0]), "=r"(r[1]), "=r"(r[2]), "=r"(r[3]) : "r"(addr));
}
__device__ __forceinline__ void mma_s8(int* d, const uint32_t* a, const uint32_t* b) {
    asm volatile("mma.sync.aligned.m16n8k32.row.col.s32.s8.s8.s32 "
        "{%0,%1,%2,%3}, {%4,%5,%6,%7}, {%8,%9}, {%0,%1,%2,%3};"
        : "+r"(d[0]), "+r"(d[1]), "+r"(d[2]), "+r"(d[3])
        : "r"(a[0]), "r"(a[1]), "r"(a[2]), "r"(a[3]), "r"(b[0]), "r"(b[1]));
}
__device__ __forceinline__ uint32_t swz(int r, int v) {
    return (uint32_t)((r * 4 + (v ^ ((r >> 1) & 3))) * 16);
}

__global__ void init_kernel() {
    int i = blockIdx.x * blockDim.x + threadIdx.x;
    if (i < LC * KC) g_counts[i] = 0;
    if (i == 0) g_commit = 0.0;
}

// warp per row: amax + int8 quantize of z
__global__ void quant_z_kernel(const float* __restrict__ z) {
    int row = (blockIdx.x * blockDim.x + threadIdx.x) >> 5;
    int lane = threadIdx.x & 31;
    if (row >= NPTS) return;
    const float4* src = (const float4*)(z + (size_t)row * DD);
    float a[16], amax = 0.f;
    #pragma unroll
    for (int j = 0; j < 4; j++) {
        float4 v = src[j * 32 + lane];
        a[j*4+0] = v.x; a[j*4+1] = v.y; a[j*4+2] = v.z; a[j*4+3] = v.w;
        amax = fmaxf(amax, fmaxf(fmaxf(fabsf(v.x), fabsf(v.y)), fmaxf(fabsf(v.z), fabsf(v.w))));
    }
    #pragma unroll
    for (int o = 16; o; o >>= 1) amax = fmaxf(amax, __shfl_xor_sync(0xffffffffu, amax, o));
    amax = fmaxf(amax, 1e-30f);
    float inv_s = 127.0f / amax;
    #pragma unroll
    for (int j = 0; j < 4; j++) {
        char4 q;
        q.x = (char)__float2int_rn(a[j*4+0] * inv_s);
        q.y = (char)__float2int_rn(a[j*4+1] * inv_s);
        q.z = (char)__float2int_rn(a[j*4+2] * inv_s);
        q.w = (char)__float2int_rn(a[j*4+3] * inv_s);
        *(char4*)(g_ai8 + (size_t)row * DD + (j * 32 + lane) * 4) = q;
    }
    if (lane == 0) g_sa[row] = amax * (1.0f / 127.0f);
}

// warp per code row: amax + quantize + 0.5*||E||^2
__global__ void quant_cb_kernel(const float* __restrict__ cb) {
    int row = (blockIdx.x * blockDim.x + threadIdx.x) >> 5;
    int lane = threadIdx.x & 31;
    if (row >= LC * KC) return;
    const float4* src = (const float4*)(cb + (size_t)row * DD);
    float a[16], amax = 0.f, ss = 0.f;
    #pragma unroll
    for (int j = 0; j < 4; j++) {
        float4 v = src[j * 32 + lane];
        a[j*4+0] = v.x; a[j*4+1] = v.y; a[j*4+2] = v.z; a[j*4+3] = v.w;
        amax = fmaxf(amax, fmaxf(fmaxf(fabsf(v.x), fabsf(v.y)), fmaxf(fabsf(v.z), fabsf(v.w))));
        ss += v.x*v.x + v.y*v.y + v.z*v.z + v.w*v.w;
    }
    #pragma unroll
    for (int o = 16; o; o >>= 1) {
        amax = fmaxf(amax, __shfl_xor_sync(0xffffffffu, amax, o));
        ss += __shfl_xor_sync(0xffffffffu, ss, o);
    }
    amax = fmaxf(amax, 1e-30f);
    float inv_s = 127.0f / amax;
    #pragma unroll
    for (int j = 0; j < 4; j++) {
        char4 q;
        q.x = (char)__float2int_rn(a[j*4+0] * inv_s);
        q.y = (char)__float2int_rn(a[j*4+1] * inv_s);
        q.z = (char)__float2int_rn(a[j*4+2] * inv_s);
        q.w = (char)__float2int_rn(a[j*4+3] * inv_s);
        *(char4*)(g_bi8 + (size_t)row * DD + (j * 32 + lane) * 4) = q;
    }
    if (lane == 0) { g_sb[row] = amax * (1.0f / 127.0f); g_c[row] = 0.5f * ss; }
}

// ---- coarse int8 mma.sync GEMM 128x128 + per-tile top-4(+s5) epilogue ----
__global__ __launch_bounds__(256, 2) void gemm_kernel(int layer) {
    extern __shared__ char smem[];
    uint32_t sb = smem_u32(smem);
    int tid = threadIdx.x, wid = tid >> 5, lane = tid & 31;
    int warp_m = wid >> 2, warp_n = wid & 3;      // 2x4 warp grid, 64x32 warp tile
    int m0 = blockIdx.x * MT, n0 = blockIdx.y * NTT;
    const int8_t* __restrict__ A = g_ai8;
    const int8_t* __restrict__ B = g_bi8 + (size_t)layer * KC * DD;
    const float* __restrict__ cl = g_c + layer * KC;
    const float* __restrict__ sbl = g_sb + layer * KC;
    float* cs  = (float*)(smem + OFF_CS);
    float* sbs = (float*)(smem + OFF_SB);
    float* sas = (float*)(smem + OFF_SA);
    if (tid < NTT) { cs[tid] = cl[n0 + tid]; sbs[tid] = sbl[n0 + tid]; }
    else if (tid < NTT + MT) sas[tid - NTT] = g_sa[m0 + tid - NTT];

    // 512 A-units + 512 B-units per stage (16B each); 256 threads x 4
    auto load_stage = [&](int s, int kc) {
        uint32_t aBase = sb + s * SMEM_STAGE;
        uint32_t bBase = aBase + 8192;
        #pragma unroll
        for (int i = 0; i < 2; i++) {
            int f = tid + i * 256;
            int r = f >> 2, v = f & 3;
            const int8_t* srcA = A + (size_t)(m0 + r) * DD + kc * KT + v * 16;
            CP_ASYNC16(aBase + swz(r, v), srcA);
            const int8_t* srcB = B + (size_t)(n0 + r) * DD + kc * KT + v * 16;
            CP_ASYNC16(bBase + swz(r, v), srcB);
        }
    };

    int acc[4][4][4];
    #pragma unroll
    for (int mi = 0; mi < 4; mi++)
        #pragma unroll
        for (int ni = 0; ni < 4; ni++)
            #pragma unroll
            for (int e = 0; e < 4; e++) acc[mi][ni][e] = 0;

    #pragma unroll
    for (int s = 0; s < STAGES - 1; s++) { load_stage(s, s); CP_COMMIT(); }

    for (int kc = 0; kc < NKCH; kc++) {
        CP_WAIT2();
        __syncthreads();
        int st = kc & (STAGES - 1);
        uint32_t aBase = sb + st * SMEM_STAGE;
        uint32_t bBase = aBase + 8192;
        #pragma unroll
        for (int kk = 0; kk < 2; kk++) {   // each kk: 32 int8 k (16 b16-units)
            uint32_t af[4][4], bf[2][4];
            #pragma unroll
            for (int mi = 0; mi < 4; mi++) {
                int r = warp_m * 64 + mi * 16 + (lane & 15);
                int v = 2 * kk + (lane >> 4);
                ldmat4(af[mi], aBase + swz(r, v));
            }
            #pragma unroll
            for (int nh = 0; nh < 2; nh++) {
                int r = warp_n * 32 + nh * 16 + (lane & 7) + ((lane >> 4) << 3);
                int v = 2 * kk + ((lane >> 3) & 1);
                ldmat4(bf[nh], bBase + swz(r, v));
            }
            #pragma unroll
            for (int mi = 0; mi < 4; mi++) {
                mma_s8(acc[mi][0], af[mi], &bf[0][0]);
                mma_s8(acc[mi][1], af[mi], &bf[0][2]);
                mma_s8(acc[mi][2], af[mi], &bf[1][0]);
                mma_s8(acc[mi][3], af[mi], &bf[1][2]);
            }
        }
        __syncthreads();
        if (kc + STAGES - 1 < NKCH) load_stage((kc + STAGES - 1) & (STAGES - 1), kc + STAGES - 1);
        CP_COMMIT();
    }
    __syncthreads();

    // dump int accumulators (as float) to smem scores [128][128]
    float* scores = (float*)smem;
    int r0 = warp_m * 64 + (lane >> 2);
    int c0 = warp_n * 32 + (lane & 3) * 2;
    #pragma unroll
    for (int mi = 0; mi < 4; mi++)
        #pragma unroll
        for (int ni = 0; ni < 4; ni++) {
            int r = r0 + mi * 16, c = c0 + ni * 8;
            scores[r * NTT + c]           = (float)acc[mi][ni][0];
            scores[r * NTT + c + 1]       = (float)acc[mi][ni][1];
            scores[(r + 8) * NTT + c]     = (float)acc[mi][ni][2];
            scores[(r + 8) * NTT + c + 1] = (float)acc[mi][ni][3];
        }
    __syncthreads();

    if (tid < 128) {
        int r = tid;
        float sa = sas[r];
        float t1 = -3.0e38f, t2 = -3.0e38f, t3 = -3.0e38f, t4 = -3.0e38f, t5 = -3.0e38f;
        int j1 = 0, j2 = 0, j3 = 0, j4 = 0;
        #pragma unroll 8
        for (int j = 0; j < 32; j++) {
            int q = (j + r) & 31;
            float4 v = *(float4*)&scores[r * NTT + q * 4];
            #pragma unroll
            for (int e = 0; e < 4; e++) {
                int col = n0 + q * 4 + e;
                float sc = fmaf(sa * sbs[q * 4 + e], (&v.x)[e], -cs[q * 4 + e]);
                if (sc > t1)      { t5 = t4; t4 = t3; j4 = j3; t3 = t2; j3 = j2; t2 = t1; j2 = j1; t1 = sc; j1 = col; }
                else if (sc > t2) { t5 = t4; t4 = t3; j4 = j3; t3 = t2; j3 = j2; t2 = sc; j2 = col; }
                else if (sc > t3) { t5 = t4; t4 = t3; j4 = j3; t3 = sc; j3 = col; }
                else if (sc > t4) { t5 = t4; t4 = sc; j4 = col; }
                else if (sc > t5) { t5 = sc; }
            }
        }
        int row = m0 + r, t = blockIdx.y;
        g_ts[row * NTILES + t] = make_float4(t1, t2, t3, t4);
        g_ti[row * NTILES + t] = make_int4(j1, j2, j3, j4);
        g_s5[row * NTILES + t] = t5;
    }
}

// ---- fused exact re-rank + assign + next-layer quantize (warp per row) ----
template <bool LAST>
__global__ __launch_bounds__(128) void rerank_assign_kernel(
    const float* __restrict__ z, const float* __restrict__ cb,
    float* __restrict__ out_q, float* __restrict__ out_idx, int layer)
{
    int warp = (blockIdx.x * blockDim.x + threadIdx.x) >> 5;
    int lane = threadIdx.x & 31;
    if (warp >= NPTS) return;
    int row = warp;
    const float* Ar = (layer == 0) ? z + (size_t)row * DD : g_resid + (size_t)row * DD;
    const float* El = cb + (size_t)layer * KC * DD;
    const float* cl = g_c + layer * KC;

    float4 ts = g_ts[row * NTILES + lane];
    int4   ti = g_ti[row * NTILES + lane];
    float  s5 = g_s5[row * NTILES + lane];

    float best = ts.x;
    #pragma unroll
    for (int o = 16; o; o >>= 1) best = fmaxf(best, __shfl_xor_sync(0xffffffffu, best, o));
    float thr = best - MARGIN;
    bool slow = __any_sync(0xffffffffu, s5 >= thr);

    float a[16];
    #pragma unroll
    for (int j = 0; j < 4; j++) {
        float4 v = ((const float4*)Ar)[j * 32 + lane];
        a[j*4+0] = v.x; a[j*4+1] = v.y; a[j*4+2] = v.z; a[j*4+3] = v.w;
    }

    float bs = -3.0e38f; int bi = 0x7fffffff;
    auto eval = [&](int k) {
        const float4* E4 = (const float4*)(El + (size_t)k * DD);
        float s = 0.f;
        #pragma unroll
        for (int j = 0; j < 4; j++) {
            float4 e = E4[j * 32 + lane];
            s = fmaf(a[j*4+0], e.x, s); s = fmaf(a[j*4+1], e.y, s);
            s = fmaf(a[j*4+2], e.z, s); s = fmaf(a[j*4+3], e.w, s);
        }
        #pragma unroll
        for (int o = 16; o; o >>= 1) s += __shfl_xor_sync(0xffffffffu, s, o);
        s -= cl[k];
        if (s > bs || (s == bs && k < bi)) { bs = s; bi = k; }
    };

    if (slow) {
        for (int k = 0; k < KC; k++) eval(k);
    } else {
        unsigned m0b = __ballot_sync(0xffffffffu, ts.x >= thr);
        unsigned m1b = __ballot_sync(0xffffffffu, ts.y >= thr);
        unsigned m2b = __ballot_sync(0xffffffffu, ts.z >= thr);
        unsigned m3b = __ballot_sync(0xffffffffu, ts.w >= thr);
        int cnt = __popc(m0b) + __popc(m1b) + __popc(m2b) + __popc(m3b);
        if (cnt == 1) {
            int t = __ffs(m0b) - 1;
            bi = __shfl_sync(0xffffffffu, ti.x, t);
        } else {
            unsigned m = m0b;
            while (m) { int t = __ffs(m) - 1; m &= m - 1; eval(__shfl_sync(0xffffffffu, ti.x, t)); }
            m = m1b;
            while (m) { int t = __ffs(m) - 1; m &= m - 1; eval(__shfl_sync(0xffffffffu, ti.y, t)); }
            m = m2b;
            while (m) { int t = __ffs(m) - 1; m &= m - 1; eval(__shfl_sync(0xffffffffu, ti.z, t)); }
            m = m3b;
            while (m) { int t = __ffs(m) - 1; m &= m - 1; eval(__shfl_sync(0xffffffffu, ti.w, t)); }
        }
    }

    if (lane == 0) {
        out_idx[(size_t)row * LC + layer] = (float)bi;
        atomicAdd(&g_counts[layer * KC + bi], 1);
    }
    const float4* E4 = (const float4*)(El + (size_t)bi * DD);
    float csum = 0.f;
    float rn[16], amax = 0.f;
    #pragma unroll
    for (int j = 0; j < 4; j++) {
        float4 e = E4[j * 32 + lane];
        rn[j*4+0] = a[j*4+0] - e.x; rn[j*4+1] = a[j*4+1] - e.y;
        rn[j*4+2] = a[j*4+2] - e.z; rn[j*4+3] = a[j*4+3] - e.w;
        #pragma unroll
        for (int e2 = 0; e2 < 4; e2++) {
            csum += rn[j*4+e2] * rn[j*4+e2];
            amax = fmaxf(amax, fabsf(rn[j*4+e2]));
        }
        if (LAST) {
            float4 zv = ((const float4*)(z + (size_t)row * DD))[j * 32 + lane];
            ((float4*)(out_q + (size_t)row * DD))[j * 32 + lane] =
                make_float4(zv.x - rn[j*4+0], zv.y - rn[j*4+1], zv.z - rn[j*4+2], zv.w - rn[j*4+3]);
        } else {
            ((float4*)(g_resid + (size_t)row * DD))[j * 32 + lane] =
                make_float4(rn[j*4+0], rn[j*4+1], rn[j*4+2], rn[j*4+3]);
        }
    }
    if (!LAST) {
        #pragma unroll
        for (int o = 16; o; o >>= 1) amax = fmaxf(amax, __shfl_xor_sync(0xffffffffu, amax, o));
        amax = fmaxf(amax, 1e-30f);
        float inv_s = 127.0f / amax;
        #pragma unroll
        for (int j = 0; j < 4; j++) {
            char4 q;
            q.x = (char)__float2int_rn(rn[j*4+0] * inv_s);
            q.y = (char)__float2int_rn(rn[j*4+1] * inv_s);
            q.z = (char)__float2int_rn(rn[j*4+2] * inv_s);
            q.w = (char)__float2int_rn(rn[j*4+3] * inv_s);
            *(char4*)(g_ai8 + (size_t)row * DD + (j * 32 + lane) * 4) = q;
        }
        if (lane == 0) g_sa[row] = amax * (1.0f / 127.0f);
    }
    #pragma unroll
    for (int o = 16; o; o >>= 1) csum += __shfl_down_sync(0xffffffffu, csum, o);
    if (lane == 0) atomicAdd(&g_commit, (double)csum);
}

__global__ void perp_kernel() {
    int l = blockIdx.x, t = threadIdx.x;
    float local = 0.f;
    for (int k = t; k < KC; k += 256) {
        float p = (float)g_counts[l * KC + k] * (1.0f / (float)NPTS);
        local += p * logf(p + 1e-10f);
    }
    #pragma unroll
    for (int o = 16; o; o >>= 1) local += __shfl_down_sync(0xffffffffu, local, o);
    __shared__ float red[8];
    if ((t & 31) == 0) red[t >> 5] = local;
    __syncthreads();
    if (t == 0) {
        float s = 0.f;
        #pragma unroll
        for (int i = 0; i < 8; i++) s += red[i];
        g_perp[l] = expf(-s);
    }
}
__global__ void final_kernel(float* __restrict__ out_sc) {
    out_sc[0] = (float)(g_commit * (0.25 / (double)NQ));
    out_sc[1] = (g_perp[0] + g_perp[1] + g_perp[2]) * (1.0f / 3.0f);
}

extern "C" void kernel_launch(void* const* d_in, const int* in_sizes, int n_in,
                              void* d_out, int out_size)
{
    const float* z  = (const float*)d_in[0];
    const float* cb = (const float*)d_in[1];
    float* out = (float*)d_out;
    float* out_q   = out;
    float* out_idx = out + NQ;
    float* out_sc  = out_idx + NIDX;

    cudaFuncSetAttribute(gemm_kernel, cudaFuncAttributeMaxDynamicSharedMemorySize, SMEM_TOTAL);

    init_kernel<<<48, 256>>>();
    quant_z_kernel<<<NPTS / 8, 256>>>(z);
    quant_cb_kernel<<<(LC * KC) / 8, 256>>>(cb);

    dim3 gg(NPTS / MT, KC / NTT);
    for (int l = 0; l < LC; l++) {
        gemm_kernel<<<gg, 256, SMEM_TOTAL>>>(l);
        if (l < LC - 1)
            rerank_assign_kernel<false><<<NPTS / 4, 128>>>(z, cb, out_q, out_idx, l);
        else
            rerank_assign_kernel<true><<<NPTS / 4, 128>>>(z, cb, out_q, out_idx, l);
    }
    perp_kernel<<<LC, 256>>>();
    final_kernel<<<1, 1>>>(out_sc);
}

// round 8
// speedup vs baseline: 1.9039x; 1.0165x over previous
#include <cuda_runtime.h>
#include <cuda_bf16.h>
#include <cstdint>

#define NPTS 32768
#define DD   512
#define KC   4096
#define LC   3
#define NQ   ((size_t)NPTS * DD)
#define NIDX ((size_t)NPTS * LC)

#define MT 128
#define NTT 128
#define KT 128                   // int8 k per chunk (128 bytes/row)
#define STAGES 3
#define NKCH (DD / KT)           // 4
#define NTILES (KC / NTT)        // 32
#define MARGIN 8.0f

// stage: A 16KB + B 16KB = 32KB; 3 stages 96KB (first 64KB reused as scores); + cs/sb/sa
#define SMEM_STAGE 32768
#define OFF_CS 98304
#define OFF_SB 98816
#define OFF_SA 99328
#define SMEM_TOTAL 99840

__device__ float   g_resid[NPTS * DD];
__device__ int8_t  g_ai8[NPTS * DD];
__device__ float   g_sa[NPTS];
__device__ int8_t  g_bi8[LC * KC * DD];
__device__ float   g_sb[LC * KC];
__device__ float   g_c[LC * KC];
__device__ float4  g_ts[NPTS * NTILES];
__device__ int4    g_ti[NPTS * NTILES];
__device__ float   g_s5[NPTS * NTILES];
__device__ int     g_counts[LC * KC];
__device__ double  g_commit;
__device__ float   g_perp[LC];

__device__ __forceinline__ uint32_t smem_u32(const void* p) {
    uint32_t a;
    asm("{ .reg .u64 t; cvta.to.shared.u64 t, %1; cvt.u32.u64 %0, t; }" : "=r"(a) : "l"(p));
    return a;
}
#define CP_ASYNC16(dst, src) asm volatile("cp.async.cg.shared.global [%0], [%1], 16;" :: "r"(dst), "l"(src))
#define CP_COMMIT() asm volatile("cp.async.commit_group;" ::: "memory")
#define CP_WAIT1()  asm volatile("cp.async.wait_group 1;" ::: "memory")
#define CP_WAIT0()  asm volatile("cp.async.wait_group 0;" ::: "memory")

__device__ __forceinline__ void ldmat4(uint32_t* r, uint32_t addr) {
    asm volatile("ldmatrix.sync.aligned.m8n8.x4.shared.b16 {%0,%1,%2,%3}, [%4];"
        : "=r"(r[0]), "=r"(r[1]), "=r"(r[2]), "=r"(r[3]) : "r"(addr));
}
__device__ __forceinline__ void mma_s8(int* d, const uint32_t* a, const uint32_t* b) {
    asm volatile("mma.sync.aligned.m16n8k32.row.col.s32.s8.s8.s32 "
        "{%0,%1,%2,%3}, {%4,%5,%6,%7}, {%8,%9}, {%0,%1,%2,%3};"
        : "+r"(d[0]), "+r"(d[1]), "+r"(d[2]), "+r"(d[3])
        : "r"(a[0]), "r"(a[1]), "r"(a[2]), "r"(a[3]), "r"(b[0]), "r"(b[1]));
}
// 128B-row SW128 swizzle: byte offset for (row r, 16B-unit v), v in 0..7
__device__ __forceinline__ uint32_t swz128(int r, int v) {
    return (uint32_t)(r * 128 + ((v ^ (r & 7)) << 4));
}

__global__ void init_kernel() {
    int i = blockIdx.x * blockDim.x + threadIdx.x;
    if (i < LC * KC) g_counts[i] = 0;
    if (i == 0) g_commit = 0.0;
}

__global__ void quant_z_kernel(const float* __restrict__ z) {
    int row = (blockIdx.x * blockDim.x + threadIdx.x) >> 5;
    int lane = threadIdx.x & 31;
    if (row >= NPTS) return;
    const float4* src = (const float4*)(z + (size_t)row * DD);
    float a[16], amax = 0.f;
    #pragma unroll
    for (int j = 0; j < 4; j++) {
        float4 v = src[j * 32 + lane];
        a[j*4+0] = v.x; a[j*4+1] = v.y; a[j*4+2] = v.z; a[j*4+3] = v.w;
        amax = fmaxf(amax, fmaxf(fmaxf(fabsf(v.x), fabsf(v.y)), fmaxf(fabsf(v.z), fabsf(v.w))));
    }
    #pragma unroll
    for (int o = 16; o; o >>= 1) amax = fmaxf(amax, __shfl_xor_sync(0xffffffffu, amax, o));
    amax = fmaxf(amax, 1e-30f);
    float inv_s = 127.0f / amax;
    #pragma unroll
    for (int j = 0; j < 4; j++) {
        char4 q;
        q.x = (char)__float2int_rn(a[j*4+0] * inv_s);
        q.y = (char)__float2int_rn(a[j*4+1] * inv_s);
        q.z = (char)__float2int_rn(a[j*4+2] * inv_s);
        q.w = (char)__float2int_rn(a[j*4+3] * inv_s);
        *(char4*)(g_ai8 + (size_t)row * DD + (j * 32 + lane) * 4) = q;
    }
    if (lane == 0) g_sa[row] = amax * (1.0f / 127.0f);
}

__global__ void quant_cb_kernel(const float* __restrict__ cb) {
    int row = (blockIdx.x * blockDim.x + threadIdx.x) >> 5;
    int lane = threadIdx.x & 31;
    if (row >= LC * KC) return;
    const float4* src = (const float4*)(cb + (size_t)row * DD);
    float a[16], amax = 0.f, ss = 0.f;
    #pragma unroll
    for (int j = 0; j < 4; j++) {
        float4 v = src[j * 32 + lane];
        a[j*4+0] = v.x; a[j*4+1] = v.y; a[j*4+2] = v.z; a[j*4+3] = v.w;
        amax = fmaxf(amax, fmaxf(fmaxf(fabsf(v.x), fabsf(v.y)), fmaxf(fabsf(v.z), fabsf(v.w))));
        ss += v.x*v.x + v.y*v.y + v.z*v.z + v.w*v.w;
    }
    #pragma unroll
    for (int o = 16; o; o >>= 1) {
        amax = fmaxf(amax, __shfl_xor_sync(0xffffffffu, amax, o));
        ss += __shfl_xor_sync(0xffffffffu, ss, o);
    }
    amax = fmaxf(amax, 1e-30f);
    float inv_s = 127.0f / amax;
    #pragma unroll
    for (int j = 0; j < 4; j++) {
        char4 q;
        q.x = (char)__float2int_rn(a[j*4+0] * inv_s);
        q.y = (char)__float2int_rn(a[j*4+1] * inv_s);
        q.z = (char)__float2int_rn(a[j*4+2] * inv_s);
        q.w = (char)__float2int_rn(a[j*4+3] * inv_s);
        *(char4*)(g_bi8 + (size_t)row * DD + (j * 32 + lane) * 4) = q;
    }
    if (lane == 0) { g_sb[row] = amax * (1.0f / 127.0f); g_c[row] = 0.5f * ss; }
}

// ---- coarse int8 mma.sync GEMM 128x128 (KT=128, 3 stages, 1 sync/chunk) ----
__global__ __launch_bounds__(256, 2) void gemm_kernel(int layer) {
    extern __shared__ char smem[];
    uint32_t sb = smem_u32(smem);
    int tid = threadIdx.x, wid = tid >> 5, lane = tid & 31;
    int warp_m = wid >> 2, warp_n = wid & 3;      // 2x4 warp grid, 64x32 warp tile
    int m0 = blockIdx.x * MT, n0 = blockIdx.y * NTT;
    const int8_t* __restrict__ A = g_ai8;
    const int8_t* __restrict__ B = g_bi8 + (size_t)layer * KC * DD;
    const float* __restrict__ cl = g_c + layer * KC;
    const float* __restrict__ sbl = g_sb + layer * KC;
    float* cs  = (float*)(smem + OFF_CS);
    float* sbs = (float*)(smem + OFF_SB);
    float* sas = (float*)(smem + OFF_SA);
    if (tid < NTT) { cs[tid] = cl[n0 + tid]; sbs[tid] = sbl[n0 + tid]; }
    else if (tid < NTT + MT) sas[tid - NTT] = g_sa[m0 + tid - NTT];

    // ---- loader precompute: 1024 A + 1024 B 16B-units per stage; 256 threads x 8 ----
    const int8_t* srcA[4]; const int8_t* srcB[4]; uint32_t dst[4];
    #pragma unroll
    for (int i = 0; i < 4; i++) {
        int f = tid + i * 256;      // 0..1023
        int r = f >> 3, v = f & 7;
        srcA[i] = A + (size_t)(m0 + r) * DD + v * 16;
        srcB[i] = B + (size_t)(n0 + r) * DD + v * 16;
        dst[i] = swz128(r, v);
    }
    auto load_stage = [&](int s, int kc) {
        uint32_t aBase = sb + s * SMEM_STAGE;
        uint32_t bBase = aBase + 16384;
        int off = kc * KT;
        #pragma unroll
        for (int i = 0; i < 4; i++) {
            CP_ASYNC16(aBase + dst[i], srcA[i] + off);
            CP_ASYNC16(bBase + dst[i], srcB[i] + off);
        }
    };

    // ---- fragment address precompute ----
    int aU = lane >> 4, bU = (lane >> 3) & 1;
    uint32_t aRT[4], bRT[2];
    int aRM[4], bRM[2];
    #pragma unroll
    for (int mi = 0; mi < 4; mi++) {
        int r = warp_m * 64 + mi * 16 + (lane & 15);
        aRT[mi] = (uint32_t)(r * 128); aRM[mi] = r & 7;
    }
    #pragma unroll
    for (int nh = 0; nh < 2; nh++) {
        int r = warp_n * 32 + nh * 16 + (lane & 7) + ((lane >> 4) << 3);
        bRT[nh] = (uint32_t)(r * 128); bRM[nh] = r & 7;
    }

    int acc[4][4][4];
    #pragma unroll
    for (int mi = 0; mi < 4; mi++)
        #pragma unroll
        for (int ni = 0; ni < 4; ni++)
            #pragma unroll
            for (int e = 0; e < 4; e++) acc[mi][ni][e] = 0;

    load_stage(0, 0); CP_COMMIT();
    load_stage(1, 1); CP_COMMIT();

    for (int kc = 0; kc < NKCH; kc++) {
        CP_WAIT1();
        __syncthreads();
        if (kc + 2 < NKCH) load_stage((kc + 2) % STAGES, kc + 2);
        CP_COMMIT();
        uint32_t aBase = sb + (kc % STAGES) * SMEM_STAGE;
        uint32_t bBase = aBase + 16384;
        #pragma unroll
        for (int kk = 0; kk < 4; kk++) {   // each kk: 32 int8 k
            uint32_t af[4][4], bf[2][4];
            #pragma unroll
            for (int mi = 0; mi < 4; mi++)
                ldmat4(af[mi], aBase + aRT[mi] + ((uint32_t)((2 * kk + aU) ^ aRM[mi]) << 4));
            #pragma unroll
            for (int nh = 0; nh < 2; nh++)
                ldmat4(bf[nh], bBase + bRT[nh] + ((uint32_t)((2 * kk + bU) ^ bRM[nh]) << 4));
            #pragma unroll
            for (int mi = 0; mi < 4; mi++) {
                mma_s8(acc[mi][0], af[mi], &bf[0][0]);
                mma_s8(acc[mi][1], af[mi], &bf[0][2]);
                mma_s8(acc[mi][2], af[mi], &bf[1][0]);
                mma_s8(acc[mi][3], af[mi], &bf[1][2]);
            }
        }
    }
    CP_WAIT0();
    __syncthreads();

    // dump int accumulators (as float) to smem scores [128][128]
    float* scores = (float*)smem;
    int r0 = warp_m * 64 + (lane >> 2);
    int c0 = warp_n * 32 + (lane & 3) * 2;
    #pragma unroll
    for (int mi = 0; mi < 4; mi++)
        #pragma unroll
        for (int ni = 0; ni < 4; ni++) {
            int r = r0 + mi * 16, c = c0 + ni * 8;
            scores[r * NTT + c]           = (float)acc[mi][ni][0];
            scores[r * NTT + c + 1]       = (float)acc[mi][ni][1];
            scores[(r + 8) * NTT + c]     = (float)acc[mi][ni][2];
            scores[(r + 8) * NTT + c + 1] = (float)acc[mi][ni][3];
        }
    __syncthreads();

    if (tid < 128) {
        int r = tid;
        float sa = sas[r];
        float t1 = -3.0e38f, t2 = -3.0e38f, t3 = -3.0e38f, t4 = -3.0e38f, t5 = -3.0e38f;
        int j1 = 0, j2 = 0, j3 = 0, j4 = 0;
        #pragma unroll 8
        for (int j = 0; j < 32; j++) {
            int q = (j + r) & 31;
            float4 v = *(float4*)&scores[r * NTT + q * 4];
            #pragma unroll
            for (int e = 0; e < 4; e++) {
                int col = n0 + q * 4 + e;
                float sc = fmaf(sa * sbs[q * 4 + e], (&v.x)[e], -cs[q * 4 + e]);
                if (sc > t1)      { t5 = t4; t4 = t3; j4 = j3; t3 = t2; j3 = j2; t2 = t1; j2 = j1; t1 = sc; j1 = col; }
                else if (sc > t2) { t5 = t4; t4 = t3; j4 = j3; t3 = t2; j3 = j2; t2 = sc; j2 = col; }
                else if (sc > t3) { t5 = t4; t4 = t3; j4 = j3; t3 = sc; j3 = col; }
                else if (sc > t4) { t5 = t4; t4 = sc; j4 = col; }
                else if (sc > t5) { t5 = sc; }
            }
        }
        int row = m0 + r, t = blockIdx.y;
        g_ts[row * NTILES + t] = make_float4(t1, t2, t3, t4);
        g_ti[row * NTILES + t] = make_int4(j1, j2, j3, j4);
        g_s5[row * NTILES + t] = t5;
    }
}

// ---- fused exact re-rank + assign + next-layer quantize (warp per row) ----
template <bool LAST>
__global__ __launch_bounds__(128) void rerank_assign_kernel(
    const float* __restrict__ z, const float* __restrict__ cb,
    float* __restrict__ out_q, float* __restrict__ out_idx, int layer)
{
    int warp = (blockIdx.x * blockDim.x + threadIdx.x) >> 5;
    int lane = threadIdx.x & 31;
    if (warp >= NPTS) return;
    int row = warp;
    const float* Ar = (layer == 0) ? z + (size_t)row * DD : g_resid + (size_t)row * DD;
    const float* El = cb + (size_t)layer * KC * DD;
    const float* cl = g_c + layer * KC;

    float4 ts = g_ts[row * NTILES + lane];
    int4   ti = g_ti[row * NTILES + lane];
    float  s5 = g_s5[row * NTILES + lane];

    float best = ts.x;
    #pragma unroll
    for (int o = 16; o; o >>= 1) best = fmaxf(best, __shfl_xor_sync(0xffffffffu, best, o));
    float thr = best - MARGIN;
    bool slow = __any_sync(0xffffffffu, s5 >= thr);

    float a[16];
    #pragma unroll
    for (int j = 0; j < 4; j++) {
        float4 v = ((const float4*)Ar)[j * 32 + lane];
        a[j*4+0] = v.x; a[j*4+1] = v.y; a[j*4+2] = v.z; a[j*4+3] = v.w;
    }

    float bs = -3.0e38f; int bi = 0x7fffffff;
    auto eval = [&](int k) {
        const float4* E4 = (const float4*)(El + (size_t)k * DD);
        float s = 0.f;
        #pragma unroll
        for (int j = 0; j < 4; j++) {
            float4 e = E4[j * 32 + lane];
            s = fmaf(a[j*4+0], e.x, s); s = fmaf(a[j*4+1], e.y, s);
            s = fmaf(a[j*4+2], e.z, s); s = fmaf(a[j*4+3], e.w, s);
        }
        #pragma unroll
        for (int o = 16; o; o >>= 1) s += __shfl_xor_sync(0xffffffffu, s, o);
        s -= cl[k];
        if (s > bs || (s == bs && k < bi)) { bs = s; bi = k; }
    };

    if (slow) {
        for (int k = 0; k < KC; k++) eval(k);
    } else {
        unsigned m0b = __ballot_sync(0xffffffffu, ts.x >= thr);
        unsigned m1b = __ballot_sync(0xffffffffu, ts.y >= thr);
        unsigned m2b = __ballot_sync(0xffffffffu, ts.z >= thr);
        unsigned m3b = __ballot_sync(0xffffffffu, ts.w >= thr);
        int cnt = __popc(m0b) + __popc(m1b) + __popc(m2b) + __popc(m3b);
        if (cnt == 1) {
            int t = __ffs(m0b) - 1;
            bi = __shfl_sync(0xffffffffu, ti.x, t);
        } else {
            unsigned m = m0b;
            while (m) { int t = __ffs(m) - 1; m &= m - 1; eval(__shfl_sync(0xffffffffu, ti.x, t)); }
            m = m1b;
            while (m) { int t = __ffs(m) - 1; m &= m - 1; eval(__shfl_sync(0xffffffffu, ti.y, t)); }
            m = m2b;
            while (m) { int t = __ffs(m) - 1; m &= m - 1; eval(__shfl_sync(0xffffffffu, ti.z, t)); }
            m = m3b;
            while (m) { int t = __ffs(m) - 1; m &= m - 1; eval(__shfl_sync(0xffffffffu, ti.w, t)); }
        }
    }

    if (lane == 0) {
        out_idx[(size_t)row * LC + layer] = (float)bi;
        atomicAdd(&g_counts[layer * KC + bi], 1);
    }
    const float4* E4 = (const float4*)(El + (size_t)bi * DD);
    float csum = 0.f;
    float rn[16], amax = 0.f;
    #pragma unroll
    for (int j = 0; j < 4; j++) {
        float4 e = E4[j * 32 + lane];
        rn[j*4+0] = a[j*4+0] - e.x; rn[j*4+1] = a[j*4+1] - e.y;
        rn[j*4+2] = a[j*4+2] - e.z; rn[j*4+3] = a[j*4+3] - e.w;
        #pragma unroll
        for (int e2 = 0; e2 < 4; e2++) {
            csum += rn[j*4+e2] * rn[j*4+e2];
            amax = fmaxf(amax, fabsf(rn[j*4+e2]));
        }
        if (LAST) {
            float4 zv = ((const float4*)(z + (size_t)row * DD))[j * 32 + lane];
            ((float4*)(out_q + (size_t)row * DD))[j * 32 + lane] =
                make_float4(zv.x - rn[j*4+0], zv.y - rn[j*4+1], zv.z - rn[j*4+2], zv.w - rn[j*4+3]);
        } else {
            ((float4*)(g_resid + (size_t)row * DD))[j * 32 + lane] =
                make_float4(rn[j*4+0], rn[j*4+1], rn[j*4+2], rn[j*4+3]);
        }
    }
    if (!LAST) {
        #pragma unroll
        for (int o = 16; o; o >>= 1) amax = fmaxf(amax, __shfl_xor_sync(0xffffffffu, amax, o));
        amax = fmaxf(amax, 1e-30f);
        float inv_s = 127.0f / amax;
        #pragma unroll
        for (int j = 0; j < 4; j++) {
            char4 q;
            q.x = (char)__float2int_rn(rn[j*4+0] * inv_s);
            q.y = (char)__float2int_rn(rn[j*4+1] * inv_s);
            q.z = (char)__float2int_rn(rn[j*4+2] * inv_s);
            q.w = (char)__float2int_rn(rn[j*4+3] * inv_s);
            *(char4*)(g_ai8 + (size_t)row * DD + (j * 32 + lane) * 4) = q;
        }
        if (lane == 0) g_sa[row] = amax * (1.0f / 127.0f);
    }
    #pragma unroll
    for (int o = 16; o; o >>= 1) csum += __shfl_down_sync(0xffffffffu, csum, o);
    if (lane == 0) atomicAdd(&g_commit, (double)csum);
}

__global__ void perp_kernel() {
    int l = blockIdx.x, t = threadIdx.x;
    float local = 0.f;
    for (int k = t; k < KC; k += 256) {
        float p = (float)g_counts[l * KC + k] * (1.0f / (float)NPTS);
        local += p * logf(p + 1e-10f);
    }
    #pragma unroll
    for (int o = 16; o; o >>= 1) local += __shfl_down_sync(0xffffffffu, local, o);
    __shared__ float red[8];
    if ((t & 31) == 0) red[t >> 5] = local;
    __syncthreads();
    if (t == 0) {
        float s = 0.f;
        #pragma unroll
        for (int i = 0; i < 8; i++) s += red[i];
        g_perp[l] = expf(-s);
    }
}
__global__ void final_kernel(float* __restrict__ out_sc) {
    out_sc[0] = (float)(g_commit * (0.25 / (double)NQ));
    out_sc[1] = (g_perp[0] + g_perp[1] + g_perp[2]) * (1.0f / 3.0f);
}

extern "C" void kernel_launch(void* const* d_in, const int* in_sizes, int n_in,
                              void* d_out, int out_size)
{
    const float* z  = (const float*)d_in[0];
    const float* cb = (const float*)d_in[1];
    float* out = (float*)d_out;
    float* out_q   = out;
    float* out_idx = out + NQ;
    float* out_sc  = out_idx + NIDX;

    cudaFuncSetAttribute(gemm_kernel, cudaFuncAttributeMaxDynamicSharedMemorySize, SMEM_TOTAL);

    init_kernel<<<48, 256>>>();
    quant_z_kernel<<<NPTS / 8, 256>>>(z);
    quant_cb_kernel<<<(LC * KC) / 8, 256>>>(cb);

    dim3 gg(NPTS / MT, KC / NTT);
    for (int l = 0; l < LC; l++) {
        gemm_kernel<<<gg, 256, SMEM_TOTAL>>>(l);
        if (l < LC - 1)
            rerank_assign_kernel<false><<<NPTS / 4, 128>>>(z, cb, out_q, out_idx, l);
        else
            rerank_assign_kernel<true><<<NPTS / 4, 128>>>(z, cb, out_q, out_idx, l);
    }
    perp_kernel<<<LC, 256>>>();
    final_kernel<<<1, 1>>>(out_sc);
}